// round 6
// baseline (speedup 1.0000x reference)
#include <cuda_runtime.h>
#include <cstdint>

// CIN (xDeepFM) fused kernel: one CTA per batch row, 512 threads.
// 3 CIN layers as SMEM-resident GEMMs with on-the-fly outer-product B tiles.
// k-sliced register blocking: every layer runs a uniform 8x4 per-thread tile
// (16 packed f32x2 FMAs per processed k), with S=512/(2L) k-slices reduced
// once per layer via packed adds.

#define BATCH 2048
#define FIELD 39
#define DIM   64
#define KT    32
#define NTHR  512

#define L0 256
#define L1 128
#define L2 64
#define LTOT (L0 + L1 + L2)

#define WSTRIDE (KT * L0)     // 8192 floats per W buffer
#define BSTRIDE (KT * DIM)    // 2048 floats per B buffer

typedef unsigned long long ull;

__device__ __forceinline__ ull dup2(float v) {
    ull r; asm("mov.b64 %0, {%1, %1};" : "=l"(r) : "f"(v)); return r;
}
__device__ __forceinline__ void fma2(ull& d, ull a, ull b) {
    asm("fma.rn.f32x2 %0, %1, %2, %3;" : "=l"(d) : "l"(a), "l"(b), "l"(d));
}
__device__ __forceinline__ ull add2(ull a, ull b) {
    ull d; asm("add.rn.f32x2 %0, %1, %2;" : "=l"(d) : "l"(a), "l"(b));
    return d;
}
__device__ __forceinline__ float2 unpack2(ull v) {
    float2 f; asm("mov.b64 {%0, %1}, %2;" : "=f"(f.x), "=f"(f.y) : "l"(v));
    return f;
}

// SMEM layout (floats)
#define OFF_X0 0
#define OFF_H0 (OFF_X0 + FIELD * DIM)          // 2496
#define OFF_H1 (OFF_H0 + L0 * DIM)
#define OFF_H2 (OFF_H1 + L1 * DIM)
#define OFF_WS (OFF_H2 + L2 * DIM)             // 2*WSTRIDE
#define OFF_BS (OFF_WS + 2 * WSTRIDE)          // 2*BSTRIDE
#define SMEM_FLOATS (OFF_BS + 2 * BSTRIDE)     // 51648 -> 206,592 B
#define SMEM_BYTES (SMEM_FLOATS * 4)

// One CIN layer: C[L,64] = W^T[L,K] * P[K,64], P[(i,j),d]=x0[i,d]*hprev[j,d]
// Uniform per-thread tile: TL=8 l's (4 packed pairs) x TD=4 d's.
// S = 512/(2L) k-slices; partials reduced via SMEM scratch (aliases Ws).
template<int L, int FK>
__device__ __forceinline__ void cin_layer(
    const float* __restrict__ Wg, const float* __restrict__ bias,
    const float* __restrict__ x0s, const float* __restrict__ hprev,
    float* __restrict__ hout, float* __restrict__ Ws, float* __restrict__ Bs,
    float* __restrict__ scratch)
{
    constexpr int TL = 8, TD = 4, NP = 4;
    constexpr int S  = NTHR / (2 * L);          // 1 / 2 / 4
    constexpr int K  = FIELD * FK;
    constexpr int T  = (K + KT - 1) / KT;
    constexpr int NW4 = (KT * L) / (4 * NTHR);  // 4 / 2 / 1

    const int tid   = threadIdx.x;
    const int slice = tid / (2 * L);            // 0..S-1
    const int sid   = tid % (2 * L);
    const int lg    = sid >> 4;
    const int dg    = sid & 15;
    const int l0    = lg * TL;
    const int d0    = dg * TD;

    ull acc[NP][TD];
    #pragma unroll
    for (int p = 0; p < NP; p++)
        #pragma unroll
        for (int q = 0; q < TD; q++) acc[p][q] = 0ull;

    float4 wreg[NW4];

    // ---- per-k body ----
    auto body = [&](const float* Wsb, const float* Bsb, int kk) {
        const float4 bf = *(const float4*)(Bsb + kk * DIM + d0);
        ull bv[TD];
        bv[0] = dup2(bf.x); bv[1] = dup2(bf.y);
        bv[2] = dup2(bf.z); bv[3] = dup2(bf.w);
        const ulonglong2* wp = (const ulonglong2*)(Wsb + kk * L + l0);
        const ulonglong2 wa = wp[0];
        const ulonglong2 wb = wp[1];
        ull w[NP] = {wa.x, wa.y, wb.x, wb.y};
        #pragma unroll
        for (int p = 0; p < NP; p++)
            #pragma unroll
            for (int q = 0; q < TD; q++) fma2(acc[p][q], w[p], bv[q]);
    };

    // ---- prologue: stage tile 0 directly ----
    {
        const int kcnt = min(KT, K);
        const int n4 = kcnt * L / 4;
        const float4* src = (const float4*)Wg;
        float4* dst = (float4*)Ws;
        for (int idx = tid; idx < n4; idx += NTHR) dst[idx] = src[idx];
        const int n = kcnt * DIM;
        for (int e = tid; e < n; e += NTHR) {
            const int kk = e >> 6, d = e & 63;
            const int i = kk / FK, j = kk - i * FK;
            Bs[e] = x0s[i * DIM + d] * hprev[j * DIM + d];
        }
    }
    __syncthreads();

    for (int t = 0; t < T; t++) {
        const int cur  = t & 1;
        const int nxt  = cur ^ 1;
        const int kcnt = min(KT, K - t * KT);
        const bool more = (t + 1 < T);
        const int nk0  = (t + 1) * KT;
        const int nn4  = more ? (min(KT, K - nk0) * L / 4) : 0;

        // issue next W tile's LDGs early (latency hides behind compute)
        if (more) {
            const float4* src = (const float4*)(Wg + (size_t)nk0 * L);
            #pragma unroll
            for (int u = 0; u < NW4; u++) {
                const int idx = tid + u * NTHR;
                if (idx < nn4) wreg[u] = src[idx];
            }
        }

        // ---- compute current tile (k-sliced) ----
        {
            const float* Wsb = Ws + cur * WSTRIDE;
            const float* Bsb = Bs + cur * BSTRIDE;
            if (kcnt == KT) {
                #pragma unroll 8
                for (int kk = slice; kk < KT; kk += S) body(Wsb, Bsb, kk);
            } else {
                for (int kk = slice; kk < kcnt; kk += S) body(Wsb, Bsb, kk);
            }
        }

        // ---- commit next tile ----
        if (more) {
            float4* dst = (float4*)(Ws + nxt * WSTRIDE);
            #pragma unroll
            for (int u = 0; u < NW4; u++) {
                const int idx = tid + u * NTHR;
                if (idx < nn4) dst[idx] = wreg[u];
            }
            float* Bsb = Bs + nxt * BSTRIDE;
            const int n = min(KT, K - nk0) * DIM;
            for (int e = tid; e < n; e += NTHR) {
                const int kk = e >> 6, d = e & 63;
                const int gk = nk0 + kk;
                const int i = gk / FK, j = gk - i * FK;
                Bsb[e] = x0s[i * DIM + d] * hprev[j * DIM + d];
            }
        }
        __syncthreads();
    }

    // ---- k-slice reduction (scratch aliases Ws; all reads of Ws done) ----
    if (S > 1) {
        if (slice != 0) {
            ull* dst = (ull*)(scratch +
                ((size_t)(slice - 1) * 2 * L + sid) * (NP * TD * 2));
            #pragma unroll
            for (int p = 0; p < NP; p++)
                #pragma unroll
                for (int q = 0; q < TD; q++) dst[p * TD + q] = acc[p][q];
        }
        __syncthreads();
        if (slice == 0) {
            #pragma unroll
            for (int s = 1; s < S; s++) {
                const ull* src = (const ull*)(scratch +
                    ((size_t)(s - 1) * 2 * L + sid) * (NP * TD * 2));
                #pragma unroll
                for (int p = 0; p < NP; p++)
                    #pragma unroll
                    for (int q = 0; q < TD; q++)
                        acc[p][q] = add2(acc[p][q], src[p * TD + q]);
            }
        }
    }

    // ---- epilogue: add bias, store hout [l][d] (slice 0 only) ----
    if (slice == 0) {
        #pragma unroll
        for (int p = 0; p < NP; p++) {
            const int la = l0 + 2 * p;
            const float ba = bias[la];
            const float bb = bias[la + 1];
            #pragma unroll
            for (int q = 0; q < TD; q++) {
                const float2 v = unpack2(acc[p][q]);
                hout[la * DIM + d0 + q]       = v.x + ba;
                hout[(la + 1) * DIM + d0 + q] = v.y + bb;
            }
        }
    }
}

__global__ void __launch_bounds__(NTHR, 1) cin_kernel(
    const void* __restrict__ feat_ids_raw,
    const float* __restrict__ emb,
    const float* __restrict__ W0, const float* __restrict__ b0,
    const float* __restrict__ W1, const float* __restrict__ b1,
    const float* __restrict__ W2, const float* __restrict__ b2,
    float* __restrict__ out)
{
    extern __shared__ float sm[];
    float* x0s = sm + OFF_X0;
    float* h0  = sm + OFF_H0;
    float* h1  = sm + OFF_H1;
    float* h2  = sm + OFF_H2;
    float* Ws  = sm + OFF_WS;
    float* Bs  = sm + OFF_BS;
    float* scratch = sm + OFF_WS;   // reused after GEMM loop

    __shared__ long long sids[FIELD];
    __shared__ int is64flag;

    const int b   = blockIdx.x;
    const int tid = threadIdx.x;

    // Detect id element width (int64 vs int32): int64 ids < 13105 => every
    // high 32-bit word is zero.
    if (tid == 0) {
        const unsigned int* w = (const unsigned int*)feat_ids_raw;
        int f = 1;
        #pragma unroll
        for (int t = 0; t < 32; t++)
            if (w[2 * t + 1] != 0u) { f = 0; break; }
        is64flag = f;
    }
    __syncthreads();

    if (tid < FIELD) {
        long long id;
        if (is64flag)
            id = ((const long long*)feat_ids_raw)[(size_t)b * FIELD + tid];
        else
            id = ((const int*)feat_ids_raw)[(size_t)b * FIELD + tid];
        sids[tid] = id;
    }
    __syncthreads();

    // Gather x0 = emb[feat_ids[b]]  -> SMEM [39][64]
    for (int t = tid; t < FIELD * DIM; t += NTHR) {
        const int r = t >> 6;
        const int d = t & 63;
        x0s[t] = emb[(size_t)sids[r] * DIM + d];
    }
    __syncthreads();

    cin_layer<L0, FIELD>(W0, b0, x0s, x0s, h0, Ws, Bs, scratch);
    __syncthreads();
    cin_layer<L1, L0>(W1, b1, x0s, h0, h1, Ws, Bs, scratch);
    __syncthreads();
    cin_layer<L2, L1>(W2, b2, x0s, h1, h2, Ws, Bs, scratch);
    __syncthreads();

    // Final reduce over embedding dim, write [b, 448]
    float* outb = out + (size_t)b * LTOT;
    for (int l = tid; l < LTOT; l += NTHR) {
        const float* src = (l < L0) ? (h0 + l * DIM)
                         : (l < L0 + L1) ? (h1 + (l - L0) * DIM)
                         : (h2 + (l - L0 - L1) * DIM);
        const float4* s4 = (const float4*)src;
        float s = 0.f;
        #pragma unroll
        for (int d = 0; d < DIM / 4; d++) {
            const float4 v = s4[d];
            s += (v.x + v.y) + (v.z + v.w);
        }
        outb[l] = s;
    }
}

extern "C" void kernel_launch(void* const* d_in, const int* in_sizes, int n_in,
                              void* d_out, int out_size) {
    const void*  feat = d_in[0];
    const float* emb  = (const float*)d_in[1];
    const float* W0   = (const float*)d_in[2];
    const float* b0   = (const float*)d_in[3];
    const float* W1   = (const float*)d_in[4];
    const float* b1   = (const float*)d_in[5];
    const float* W2   = (const float*)d_in[6];
    const float* b2   = (const float*)d_in[7];
    float* out = (float*)d_out;

    cudaFuncSetAttribute(cin_kernel,
                         cudaFuncAttributeMaxDynamicSharedMemorySize,
                         SMEM_BYTES);
    cin_kernel<<<BATCH, NTHR, SMEM_BYTES>>>(feat, emb, W0, b0, W1, b1,
                                            W2, b2, out);
}

// round 8
// speedup vs baseline: 2.2844x; 2.2844x over previous
#include <cuda_runtime.h>
#include <cuda_bf16.h>
#include <cstdint>

#define FIELD 39
#define DIM   64
#define NTHR  512
#define BATCH 2048
#define TILE_ELEMS 8192   // 128x64 bf16 prep tile

// SMEM layout (bytes)
#define HP0  40
#define HPH0 264
#define HPH1 136
#define SO_X0T 0
#define SO_H0T (SO_X0T + 64*HP0*4)     // 10240
#define SO_H1T (SO_H0T + 64*HPH0*4)    // 77824
#define SO_B   (SO_H1T + 64*HPH1*4)    // 112640 ; 2 stages x (hi8K+lo8K)
#define SO_A   (SO_B + 32768)          // 145408 ; 64KB A region
#define SMEM_BYTES (SO_A + 65536)      // 210944

__device__ __align__(16) unsigned short gA0h[48u*TILE_ELEMS];
__device__ __align__(16) unsigned short gA0l[48u*TILE_ELEMS];
__device__ __align__(16) unsigned short gA1h[156u*TILE_ELEMS];
__device__ __align__(16) unsigned short gA1l[156u*TILE_ELEMS];
__device__ __align__(16) unsigned short gA2h[78u*TILE_ELEMS];
__device__ __align__(16) unsigned short gA2l[78u*TILE_ELEMS];

__device__ __forceinline__ uint32_t swz(uint32_t off) {
    return off ^ ((off >> 3) & 0x70);
}
__device__ __forceinline__ void ldm4(uint32_t a, uint32_t r[4]) {
    asm volatile("ldmatrix.sync.aligned.m8n8.x4.shared.b16 {%0,%1,%2,%3}, [%4];"
                 : "=r"(r[0]), "=r"(r[1]), "=r"(r[2]), "=r"(r[3]) : "r"(a));
}
__device__ __forceinline__ void mma16816(float c[4], const uint32_t a[4],
                                         uint32_t b0, uint32_t b1) {
    asm volatile("mma.sync.aligned.m16n8k16.row.col.f32.bf16.bf16.f32 "
                 "{%0,%1,%2,%3},{%4,%5,%6,%7},{%8,%9},{%0,%1,%2,%3};"
                 : "+f"(c[0]), "+f"(c[1]), "+f"(c[2]), "+f"(c[3])
                 : "r"(a[0]), "r"(a[1]), "r"(a[2]), "r"(a[3]), "r"(b0), "r"(b1));
}
__device__ __forceinline__ unsigned short bfb(__nv_bfloat16 h) {
    return *(unsigned short*)&h;
}
__device__ __forceinline__ uint32_t split2(float a, float b, uint32_t& lo) {
    __nv_bfloat16 ha = __float2bfloat16(a), hb = __float2bfloat16(b);
    __nv_bfloat16 la = __float2bfloat16(a - __bfloat162float(ha));
    __nv_bfloat16 lb = __float2bfloat16(b - __bfloat162float(hb));
    lo = (uint32_t)bfb(la) | ((uint32_t)bfb(lb) << 16);
    return (uint32_t)bfb(ha) | ((uint32_t)bfb(hb) << 16);
}

// ---- prep: W -> swizzle-baked bf16 hi/lo W^T tile images ----
__global__ void prep_kernel(const float* __restrict__ W0,
                            const float* __restrict__ W1,
                            const float* __restrict__ W2) {
    const int tile = blockIdx.x;
    const float* W; unsigned short *Ah, *Al; int K, Lv, kt, mt;
    if (tile < 48)       { kt = tile >> 1; mt = tile & 1; W = W0; K = 1521; Lv = 256;
                           Ah = gA0h + (size_t)tile*TILE_ELEMS; Al = gA0l + (size_t)tile*TILE_ELEMS; }
    else if (tile < 204) { int u = tile - 48;  kt = u; mt = 0; W = W1; K = 9984; Lv = 128;
                           Ah = gA1h + (size_t)u*TILE_ELEMS; Al = gA1l + (size_t)u*TILE_ELEMS; }
    else                 { int u = tile - 204; kt = u; mt = 0; W = W2; K = 4992; Lv = 64;
                           Ah = gA2h + (size_t)u*TILE_ELEMS; Al = gA2l + (size_t)u*TILE_ELEMS; }
    for (int it = threadIdx.x; it < 1024; it += blockDim.x) {
        const int row = it & 127, cg = it >> 7;
        const int l = mt * 128 + row;
        uint32_t hw[4], lw[4];
        #pragma unroll
        for (int p = 0; p < 4; p++) {
            float v0 = 0.f, v1 = 0.f;
            const int k0 = kt * 64 + cg * 8 + 2 * p;
            if (l < Lv) {
                if (k0     < K) v0 = W[(size_t)k0 * Lv + l];
                if (k0 + 1 < K) v1 = W[(size_t)(k0 + 1) * Lv + l];
            }
            hw[p] = split2(v0, v1, lw[p]);
        }
        const uint32_t sw = swz((uint32_t)(row * 128 + cg * 16));
        *(uint4*)((char*)Ah + sw) = make_uint4(hw[0], hw[1], hw[2], hw[3]);
        *(uint4*)((char*)Al + sw) = make_uint4(lw[0], lw[1], lw[2], lw[3]);
    }
}

// ---- build one B chunk: B[d][k] = x0[i,d]*h[j,d], bf16 hi/lo, swizzled ----
template<int FK, int HPREV>
__device__ __forceinline__ void build_b(char* smem, int t, uint32_t bst,
                                        const float* __restrict__ hprevT) {
    const int tid = threadIdx.x;
    const float* x0T = (const float*)(smem + SO_X0T);
    const int d = tid >> 3, g = tid & 7;
    const int kb = t * 64 + g * 8;
    float v[8];
    if (FK == FIELD) {
        #pragma unroll
        for (int e = 0; e < 8; e++) {
            const int k = kb + e, i = k / FIELD, j = k - i * FIELD;
            v[e] = x0T[d * HP0 + i] * x0T[d * HP0 + j];
        }
    } else {
        const int i = kb / FK, j0 = kb % FK;
        const float xv = x0T[d * HP0 + i];
        const float4 a = *(const float4*)(hprevT + d * HPREV + j0);
        const float4 b = *(const float4*)(hprevT + d * HPREV + j0 + 4);
        v[0]=xv*a.x; v[1]=xv*a.y; v[2]=xv*a.z; v[3]=xv*a.w;
        v[4]=xv*b.x; v[5]=xv*b.y; v[6]=xv*b.z; v[7]=xv*b.w;
    }
    uint32_t hw[4], lw[4];
    #pragma unroll
    for (int p = 0; p < 4; p++) hw[p] = split2(v[2*p], v[2*p+1], lw[p]);
    const uint32_t sw = swz((uint32_t)(d * 128 + g * 16));
    char* bb = smem + SO_B + bst;
    *(uint4*)(bb + sw)        = make_uint4(hw[0], hw[1], hw[2], hw[3]);
    *(uint4*)(bb + 8192 + sw) = make_uint4(lw[0], lw[1], lw[2], lw[3]);
}

// ---- compute one 64-k chunk for this warp's 32x32 tile ----
template<int L>
__device__ __forceinline__ void chunk_mma(uint32_t su, uint32_t ast, uint32_t bst,
                                          int lrow, int dcol, int kk0, int kks,
                                          float acc[2][4][4]) {
    constexpr uint32_t LROWB = (L >= 128 ? 128 : L) * 128;
    const int lane = threadIdx.x & 31;
    for (int kk = kk0; kk < kk0 + kks; kk++) {
        uint32_t ah[2][4], al[2][4], bh[2][4], bl[2][4];
        const uint32_t ch = (uint32_t)((kk * 16 + (lane >> 4) * 8) * 2);
        #pragma unroll
        for (int mi = 0; mi < 2; mi++) {
            const int l = lrow + mi * 16 + (lane & 15);
            const int mt = (L == 256) ? (l >> 7) : 0;
            const int r  = (L == 256) ? (l & 127) : l;
            const uint32_t off = swz((uint32_t)(r * 128) + ch);
            const uint32_t hib = su + SO_A + ast + (uint32_t)mt * (2 * LROWB);
            ldm4(hib + off, ah[mi]);
            ldm4(hib + LROWB + off, al[mi]);
        }
        #pragma unroll
        for (int nb = 0; nb < 2; nb++) {
            const int d = dcol + nb * 16 + (lane & 15);
            const uint32_t off = swz((uint32_t)(d * 128) + ch);
            const uint32_t bb = su + SO_B + bst;
            ldm4(bb + off, bh[nb]);
            ldm4(bb + 8192 + off, bl[nb]);
        }
        #pragma unroll
        for (int mi = 0; mi < 2; mi++)
            #pragma unroll
            for (int j = 0; j < 4; j++) {
                const int nb = j >> 1, q = j & 1;
                const uint32_t h0 = bh[nb][q], h1 = bh[nb][q + 2];
                mma16816(acc[mi][j], ah[mi], h0, h1);
                mma16816(acc[mi][j], ah[mi], bl[nb][q], bl[nb][q + 2]);
                mma16816(acc[mi][j], al[mi], h0, h1);
            }
    }
}

// ---- one CIN layer ----
template<int L, int FK, int NKT, int S, int HPREV, int HPOUT>
__device__ void run_layer(char* smem, uint32_t su,
                          const unsigned short* gAh, const unsigned short* gAl,
                          const float* __restrict__ hprevT, float* houtT,
                          const float* __restrict__ biasg) {
    const int tid = threadIdx.x, wid = tid >> 5, lane = tid & 31;
    constexpr int NTL = L / 32, NTILES = NTL * 2;
    constexpr int KKS = 4 / S;
    constexpr uint32_t LROWB = (L >= 128 ? 128 : L) * 128;
    constexpr uint32_t ASTB = 2 * LROWB;          // A bytes per stage
    constexpr int NW4 = L / 32;                   // per-thread float4 (L<256)
    const int tile = wid % NTILES, slice = wid / NTILES;
    const int lrow = (tile % NTL) * 32, dcol = (tile / NTL) * 32;
    const int kk0 = slice * KKS;

    float acc[2][4][4];
    #pragma unroll
    for (int mi = 0; mi < 2; mi++)
        #pragma unroll
        for (int j = 0; j < 4; j++)
            #pragma unroll
            for (int q = 0; q < 4; q++) acc[mi][j][q] = 0.f;

    if (L == 256) {
        // single-buffered A + B (layer 0; 20% of work)
        for (int t = 0; t < NKT; t++) {
            __syncthreads();
            for (int idx = tid; idx < 4096; idx += NTHR) {
                const int q = idx >> 10, c = idx & 1023;
                const int mt = q >> 1, sp = q & 1;
                const float4 v = ((const float4*)((sp ? gA0l : gA0h) +
                                  (size_t)(t * 2 + mt) * TILE_ELEMS))[c];
                ((float4*)(smem + SO_A))[(size_t)q * 1024 + c] = v;
            }
            build_b<FK, HPREV>(smem, t, 0, hprevT);
            __syncthreads();
            chunk_mma<L>(su, 0, 0, lrow, dcol, kk0, KKS, acc);
        }
        __syncthreads();
    } else {
        // double-buffered A (LDG->reg->STS) + B
        for (int idx = tid; idx < L * 16; idx += NTHR) {
            const int sp = idx >= L * 8;
            const int u = idx - sp * L * 8;
            const float4 v = ((const float4*)(sp ? gAl : gAh))[u];
            ((float4*)(smem + SO_A))[(size_t)sp * (L * 8) + u] = v;
        }
        build_b<FK, HPREV>(smem, 0, 0, hprevT);
        __syncthreads();
        for (int t = 0; t < NKT; t++) {
            const bool more = (t + 1 < NKT);
            float4 wreg[NW4];
            if (more) {
                #pragma unroll
                for (int u = 0; u < NW4; u++) {
                    const int idx = tid + u * NTHR;
                    const int sp = idx >= L * 8;
                    const int e = idx - sp * L * 8;
                    wreg[u] = ((const float4*)((sp ? gAl : gAh) +
                               (size_t)(t + 1) * TILE_ELEMS))[e];
                }
            }
            chunk_mma<L>(su, (uint32_t)(t & 1) * ASTB, (uint32_t)(t & 1) * 16384,
                         lrow, dcol, kk0, KKS, acc);
            if (more) {
                char* ab = smem + SO_A + ((t + 1) & 1) * ASTB;
                #pragma unroll
                for (int u = 0; u < NW4; u++) {
                    const int idx = tid + u * NTHR;
                    const int sp = idx >= L * 8;
                    const int e = idx - sp * L * 8;
                    ((float4*)ab)[(size_t)sp * (L * 8) + e] = wreg[u];
                }
                build_b<FK, HPREV>(smem, t + 1, ((t + 1) & 1) * 16384, hprevT);
            }
            __syncthreads();
        }
    }

    // ---- k-slice reduction through A region (free now) ----
    if (S > 1) {
        if (slice != 0) {
            float4* dst = (float4*)(smem + SO_A +
                (size_t)(((slice - 1) * NTILES + tile) * 4096 + lane * 128));
            #pragma unroll
            for (int mi = 0; mi < 2; mi++)
                #pragma unroll
                for (int j = 0; j < 4; j++)
                    dst[mi * 4 + j] = *(float4*)acc[mi][j];
        }
        __syncthreads();
        if (slice == 0) {
            for (int s = 1; s < S; s++) {
                const float4* src = (const float4*)(smem + SO_A +
                    (size_t)(((s - 1) * NTILES + tile) * 4096 + lane * 128));
                #pragma unroll
                for (int mi = 0; mi < 2; mi++)
                    #pragma unroll
                    for (int j = 0; j < 4; j++) {
                        const float4 v = src[mi * 4 + j];
                        acc[mi][j][0] += v.x; acc[mi][j][1] += v.y;
                        acc[mi][j][2] += v.z; acc[mi][j][3] += v.w;
                    }
            }
        }
    }

    // ---- epilogue: bias + transposed store to houtT [d][l] ----
    if (slice == 0) {
        const int g = lane >> 2, t4 = lane & 3;
        #pragma unroll
        for (int mi = 0; mi < 2; mi++) {
            const int la = lrow + mi * 16 + g;
            const float b0 = biasg[la], b1 = biasg[la + 8];
            #pragma unroll
            for (int j = 0; j < 4; j++) {
                const int db = dcol + (j >> 1) * 16 + (j & 1) * 8 + 2 * t4;
                houtT[db * HPOUT + la]           = acc[mi][j][0] + b0;
                houtT[(db + 1) * HPOUT + la]     = acc[mi][j][1] + b0;
                houtT[db * HPOUT + la + 8]       = acc[mi][j][2] + b1;
                houtT[(db + 1) * HPOUT + la + 8] = acc[mi][j][3] + b1;
            }
        }
    }
    __syncthreads();
}

__global__ void __launch_bounds__(NTHR, 1)
cin_mma_kernel(const void* __restrict__ feat_ids_raw,
               const float* __restrict__ emb,
               const float* __restrict__ b0, const float* __restrict__ b1,
               const float* __restrict__ b2, float* __restrict__ out) {
    extern __shared__ char smem[];
    const uint32_t su = (uint32_t)__cvta_generic_to_shared(smem);
    const int b = blockIdx.x, tid = threadIdx.x;
    float* x0T = (float*)(smem + SO_X0T);
    float* h0T = (float*)(smem + SO_H0T);
    float* h1T = (float*)(smem + SO_H1T);
    float* h2T = (float*)(smem + SO_B);    // reused after layer-2 compute
    __shared__ long long sids[FIELD];
    __shared__ int is64flag;

    if (tid == 0) {
        const unsigned int* w = (const unsigned int*)feat_ids_raw;
        int f = 1;
        #pragma unroll
        for (int t = 0; t < 32; t++) if (w[2*t+1] != 0u) { f = 0; break; }
        is64flag = f;
    }
    __syncthreads();
    if (tid < FIELD) {
        sids[tid] = is64flag
            ? ((const long long*)feat_ids_raw)[(size_t)b * FIELD + tid]
            : (long long)((const int*)feat_ids_raw)[(size_t)b * FIELD + tid];
    }
    __syncthreads();
    for (int t = tid; t < FIELD * DIM; t += NTHR) {
        const int i = t >> 6, d = t & 63;
        x0T[d * HP0 + i] = emb[(size_t)sids[i] * DIM + d];
    }
    if (tid < 64) x0T[tid * HP0 + FIELD] = 0.f;   // zero pad col (K padding)
    __syncthreads();

    run_layer<256,  39,  24, 1, HP0,  HPH0>(smem, su, gA0h, gA0l, x0T, h0T, b0);
    run_layer<128, 256, 156, 2, HPH0, HPH1>(smem, su, gA1h, gA1l, h0T, h1T, b1);
    run_layer< 64, 128,  78, 4, HPH1,   64>(smem, su, gA2h, gA2l, h1T, h2T, b2);

    // ---- final: out[b, l] = sum_d hT[d][l] ----
    float* outb = out + (size_t)b * 448;
    for (int l = tid; l < 448; l += NTHR) {
        const float* src; int stride, col;
        if (l < 256)      { src = h0T; stride = HPH0; col = l; }
        else if (l < 384) { src = h1T; stride = HPH1; col = l - 256; }
        else              { src = h2T; stride = 64;   col = l - 384; }
        float s = 0.f;
        #pragma unroll 8
        for (int d = 0; d < DIM; d++) s += src[d * stride + col];
        outb[l] = s;
    }
}

extern "C" void kernel_launch(void* const* d_in, const int* in_sizes, int n_in,
                              void* d_out, int out_size) {
    const void*  feat = d_in[0];
    const float* emb  = (const float*)d_in[1];
    const float* W0   = (const float*)d_in[2];
    const float* b0   = (const float*)d_in[3];
    const float* W1   = (const float*)d_in[4];
    const float* b1   = (const float*)d_in[5];
    const float* W2   = (const float*)d_in[6];
    const float* b2   = (const float*)d_in[7];
    float* out = (float*)d_out;

    prep_kernel<<<282, 256>>>(W0, W1, W2);
    cudaFuncSetAttribute(cin_mma_kernel,
                         cudaFuncAttributeMaxDynamicSharedMemorySize, SMEM_BYTES);
    cin_mma_kernel<<<BATCH, NTHR, SMEM_BYTES>>>(feat, emb, b0, b1, b2, out);
}

// round 9
// speedup vs baseline: 3.0274x; 1.3252x over previous
#include <cuda_runtime.h>
#include <cuda_fp16.h>
#include <cstdint>

#define FIELD 39
#define DIM   64
#define NTHR  512
#define BATCH 2048

// SMEM layout (bytes)
#define HP0  40
#define HPH0 264
#define HPH1 136
#define SO_X0T 0
#define SO_H0T (SO_X0T + 64*HP0*4)     // 10240
#define SO_H1T (SO_H0T + 64*HPH0*4)    // 77824
#define SO_B   (SO_H1T + 64*HPH1*4)    // 112640 ; 2 stages x (hi8K+lo8K)
#define SO_A   (SO_B + 32768)          // 145408 ; 64KB A region (2 stages)
#define SMEM_BYTES (SO_A + 65536)      // 210944

// Prepped W^T fp16 tile images (swizzle baked). L0: 48x(128x64), L1: 156x(128x64),
// L2: 78x(64x64).
__device__ __align__(16) unsigned short gA0[48u  * 8192];
__device__ __align__(16) unsigned short gA1[156u * 8192];
__device__ __align__(16) unsigned short gA2[78u  * 4096];

__device__ __forceinline__ uint32_t swz(uint32_t off) {
    return off ^ ((off >> 3) & 0x70);
}
__device__ __forceinline__ void ldm4(uint32_t a, uint32_t r[4]) {
    asm volatile("ldmatrix.sync.aligned.m8n8.x4.shared.b16 {%0,%1,%2,%3}, [%4];"
                 : "=r"(r[0]), "=r"(r[1]), "=r"(r[2]), "=r"(r[3]) : "r"(a));
}
__device__ __forceinline__ void mmah(float c[4], const uint32_t a[4],
                                     uint32_t b0, uint32_t b1) {
    asm volatile("mma.sync.aligned.m16n8k16.row.col.f32.f16.f16.f32 "
                 "{%0,%1,%2,%3},{%4,%5,%6,%7},{%8,%9},{%0,%1,%2,%3};"
                 : "+f"(c[0]), "+f"(c[1]), "+f"(c[2]), "+f"(c[3])
                 : "r"(a[0]), "r"(a[1]), "r"(a[2]), "r"(a[3]), "r"(b0), "r"(b1));
}
__device__ __forceinline__ void cpasync16(uint32_t s, const void* g) {
    asm volatile("cp.async.cg.shared.global [%0], [%1], 16;" :: "r"(s), "l"(g));
}
#define CP_COMMIT() asm volatile("cp.async.commit_group;")
#define CP_WAIT0()  asm volatile("cp.async.wait_group 0;")

__device__ __forceinline__ unsigned short hbits(__half h) {
    return *(unsigned short*)&h;
}
__device__ __forceinline__ uint32_t pack2h(float a, float b) {
    return (uint32_t)hbits(__float2half_rn(a)) |
           ((uint32_t)hbits(__float2half_rn(b)) << 16);
}
__device__ __forceinline__ uint32_t split2h(float a, float b, uint32_t& lo) {
    const __half ha = __float2half_rn(a), hb = __float2half_rn(b);
    lo = pack2h(a - __half2float(ha), b - __half2float(hb));
    return (uint32_t)hbits(ha) | ((uint32_t)hbits(hb) << 16);
}

// ---- prep: W -> swizzle-baked fp16 W^T tile images ----
__global__ void prep_kernel(const float* __restrict__ W0,
                            const float* __restrict__ W1,
                            const float* __restrict__ W2) {
    const int tile = blockIdx.x;
    const float* W; unsigned short* A; int K, Lv, kt, mt, rows;
    if (tile < 48)       { kt = tile >> 1; mt = tile & 1; W = W0; K = 1521; Lv = 256;
                           rows = 128; A = gA0 + (size_t)tile * 8192; }
    else if (tile < 204) { int u = tile - 48;  kt = u; mt = 0; W = W1; K = 9984; Lv = 128;
                           rows = 128; A = gA1 + (size_t)u * 8192; }
    else                 { int u = tile - 204; kt = u; mt = 0; W = W2; K = 4992; Lv = 64;
                           rows = 64;  A = gA2 + (size_t)u * 4096; }
    for (int it = threadIdx.x; it < rows * 8; it += blockDim.x) {
        const int row = it % rows, cg = it / rows;
        const int l = mt * 128 + row;
        uint32_t hw[4];
        #pragma unroll
        for (int p = 0; p < 4; p++) {
            float v0 = 0.f, v1 = 0.f;
            const int k0 = kt * 64 + cg * 8 + 2 * p;
            if (l < Lv) {
                if (k0     < K) v0 = W[(size_t)k0 * Lv + l];
                if (k0 + 1 < K) v1 = W[(size_t)(k0 + 1) * Lv + l];
            }
            hw[p] = pack2h(v0, v1);
        }
        const uint32_t sw = swz((uint32_t)(row * 128 + cg * 16));
        *(uint4*)((char*)A + sw) = make_uint4(hw[0], hw[1], hw[2], hw[3]);
    }
}

// ---- build one 64-k B chunk: B[d][k] = x0[i,d]*h[j,d], fp16 hi/lo ----
template<int FK, int HPREV>
__device__ __forceinline__ void build_b(char* smem, int t, uint32_t bst,
                                        const float* __restrict__ hprevT) {
    const int tid = threadIdx.x;
    const float* x0T = (const float*)(smem + SO_X0T);
    const int d = tid >> 3, g = tid & 7;
    const int kb = t * 64 + g * 8;
    float v[8];
    if (FK == FIELD) {
        #pragma unroll
        for (int e = 0; e < 8; e++) {
            const int k = kb + e, i = k / FIELD, j = k - i * FIELD;
            v[e] = x0T[d * HP0 + i] * x0T[d * HP0 + j];
        }
    } else {
        const int i = kb / FK, j0 = kb % FK;
        const float xv = x0T[d * HP0 + i];
        const float4 a = *(const float4*)(hprevT + d * HPREV + j0);
        const float4 b = *(const float4*)(hprevT + d * HPREV + j0 + 4);
        v[0]=xv*a.x; v[1]=xv*a.y; v[2]=xv*a.z; v[3]=xv*a.w;
        v[4]=xv*b.x; v[5]=xv*b.y; v[6]=xv*b.z; v[7]=xv*b.w;
    }
    uint32_t hw[4], lw[4];
    #pragma unroll
    for (int p = 0; p < 4; p++) hw[p] = split2h(v[2*p], v[2*p+1], lw[p]);
    const uint32_t sw = swz((uint32_t)(d * 128 + g * 16));
    char* bb = smem + SO_B + bst;
    *(uint4*)(bb + sw)        = make_uint4(hw[0], hw[1], hw[2], hw[3]);
    *(uint4*)(bb + 8192 + sw) = make_uint4(lw[0], lw[1], lw[2], lw[3]);
}

// ---- one 64-k chunk of MMAs for this warp's 32x32 tile ----
template<int L>
__device__ __forceinline__ void chunk_mma(uint32_t su, uint32_t ast, uint32_t bst,
                                          int lrow, int dcol, int kk0, int kks,
                                          float acc[2][4][4]) {
    const int lane = threadIdx.x & 31;
    for (int kk = kk0; kk < kk0 + kks; kk++) {
        uint32_t ah[2][4], bh[2][4], bl[2][4];
        const uint32_t ch = (uint32_t)((kk * 16 + (lane >> 4) * 8) * 2);
        #pragma unroll
        for (int mi = 0; mi < 2; mi++) {
            const int l = lrow + mi * 16 + (lane & 15);
            const int mt = (L == 256) ? (l >> 7) : 0;
            const int r  = (L == 256) ? (l & 127) : l;
            ldm4(su + SO_A + ast + (uint32_t)mt * 16384u +
                 swz((uint32_t)(r * 128) + ch), ah[mi]);
        }
        #pragma unroll
        for (int nb = 0; nb < 2; nb++) {
            const int d = dcol + nb * 16 + (lane & 15);
            const uint32_t off = swz((uint32_t)(d * 128) + ch);
            ldm4(su + SO_B + bst + off, bh[nb]);
            ldm4(su + SO_B + bst + 8192 + off, bl[nb]);
        }
        #pragma unroll
        for (int mi = 0; mi < 2; mi++)
            #pragma unroll
            for (int j = 0; j < 4; j++) {
                const int nb = j >> 1, q = j & 1;
                mmah(acc[mi][j], ah[mi], bh[nb][q], bh[nb][q + 2]);
                mmah(acc[mi][j], ah[mi], bl[nb][q], bl[nb][q + 2]);
            }
    }
}

// ---- one CIN layer (all layers double-buffered, A via cp.async) ----
template<int L, int FK, int NKT, int S, int HPREV, int HPOUT>
__device__ void run_layer(char* smem, uint32_t su, const unsigned short* gA,
                          const float* __restrict__ hprevT, float* houtT,
                          const float* __restrict__ biasg) {
    const int tid = threadIdx.x, wid = tid >> 5, lane = tid & 31;
    constexpr int NTL = L / 32, NTILES = NTL * 2;
    constexpr int KKS = 4 / S;
    constexpr uint32_t ASTB = (uint32_t)L * 128u;   // stage bytes (fp16 rows)
    const int tile = wid % NTILES, slice = wid / NTILES;
    const int lrow = (tile % NTL) * 32, dcol = (tile / NTL) * 32;
    const int kk0 = slice * KKS;

    float acc[2][4][4];
    #pragma unroll
    for (int mi = 0; mi < 2; mi++)
        #pragma unroll
        for (int j = 0; j < 4; j++)
            #pragma unroll
            for (int q = 0; q < 4; q++) acc[mi][j][q] = 0.f;

    auto stage_a = [&](int t) {
        const uint32_t dst = su + SO_A + (uint32_t)(t & 1) * 32768u;
        const char* src = (const char*)gA + (size_t)t * ASTB;
        constexpr int N16 = (int)(ASTB / 16);
        for (int idx = tid; idx < N16; idx += NTHR)
            cpasync16(dst + (uint32_t)idx * 16, src + idx * 16);
        CP_COMMIT();
    };

    stage_a(0);
    build_b<FK, HPREV>(smem, 0, 0, hprevT);
    CP_WAIT0();
    __syncthreads();

    for (int t = 0; t < NKT; t++) {
        const bool more = (t + 1 < NKT);
        if (more) stage_a(t + 1);
        chunk_mma<L>(su, (uint32_t)(t & 1) * 32768u, (uint32_t)(t & 1) * 16384u,
                     lrow, dcol, kk0, KKS, acc);
        if (more) build_b<FK, HPREV>(smem, t + 1, ((t + 1) & 1) * 16384u, hprevT);
        CP_WAIT0();
        __syncthreads();
    }

    // ---- k-slice reduction via A region (idle now) ----
    if (S > 1) {
        if (slice != 0) {
            float4* dst = (float4*)(smem + SO_A +
                (size_t)(((slice - 1) * NTILES + tile) * 4096 + lane * 128));
            #pragma unroll
            for (int mi = 0; mi < 2; mi++)
                #pragma unroll
                for (int j = 0; j < 4; j++)
                    dst[mi * 4 + j] = *(float4*)acc[mi][j];
        }
        __syncthreads();
        if (slice == 0) {
            for (int s = 1; s < S; s++) {
                const float4* src = (const float4*)(smem + SO_A +
                    (size_t)(((s - 1) * NTILES + tile) * 4096 + lane * 128));
                #pragma unroll
                for (int mi = 0; mi < 2; mi++)
                    #pragma unroll
                    for (int j = 0; j < 4; j++) {
                        const float4 v = src[mi * 4 + j];
                        acc[mi][j][0] += v.x; acc[mi][j][1] += v.y;
                        acc[mi][j][2] += v.z; acc[mi][j][3] += v.w;
                    }
            }
        }
    }

    // ---- epilogue: bias + transposed store to houtT [d][l] ----
    if (slice == 0) {
        const int g = lane >> 2, t4 = lane & 3;
        #pragma unroll
        for (int mi = 0; mi < 2; mi++) {
            const int la = lrow + mi * 16 + g;
            const float b0 = biasg[la], b1 = biasg[la + 8];
            #pragma unroll
            for (int j = 0; j < 4; j++) {
                const int db = dcol + (j >> 1) * 16 + (j & 1) * 8 + 2 * t4;
                houtT[db * HPOUT + la]           = acc[mi][j][0] + b0;
                houtT[(db + 1) * HPOUT + la]     = acc[mi][j][1] + b0;
                houtT[db * HPOUT + la + 8]       = acc[mi][j][2] + b1;
                houtT[(db + 1) * HPOUT + la + 8] = acc[mi][j][3] + b1;
            }
        }
    }
    __syncthreads();
}

__global__ void __launch_bounds__(NTHR, 1)
cin_mma_kernel(const void* __restrict__ feat_ids_raw,
               const float* __restrict__ emb,
               const float* __restrict__ b0, const float* __restrict__ b1,
               const float* __restrict__ b2, float* __restrict__ out) {
    extern __shared__ char smem[];
    const uint32_t su = (uint32_t)__cvta_generic_to_shared(smem);
    const int b = blockIdx.x, tid = threadIdx.x;
    float* x0T = (float*)(smem + SO_X0T);
    float* h0T = (float*)(smem + SO_H0T);
    float* h1T = (float*)(smem + SO_H1T);
    float* h2T = (float*)(smem + SO_B);    // reused after layer-2 compute
    __shared__ long long sids[FIELD];
    __shared__ int is64flag;

    if (tid == 0) {
        const unsigned int* w = (const unsigned int*)feat_ids_raw;
        int f = 1;
        #pragma unroll
        for (int t = 0; t < 32; t++) if (w[2*t+1] != 0u) { f = 0; break; }
        is64flag = f;
    }
    __syncthreads();
    if (tid < FIELD) {
        sids[tid] = is64flag
            ? ((const long long*)feat_ids_raw)[(size_t)b * FIELD + tid]
            : (long long)((const int*)feat_ids_raw)[(size_t)b * FIELD + tid];
    }
    __syncthreads();
    for (int t = tid; t < FIELD * DIM; t += NTHR) {
        const int i = t >> 6, d = t & 63;
        x0T[d * HP0 + i] = emb[(size_t)sids[i] * DIM + d];
    }
    if (tid < 64) x0T[tid * HP0 + FIELD] = 0.f;   // zero pad col (K padding)
    __syncthreads();

    run_layer<256,  39,  24, 1, HP0,  HPH0>(smem, su, gA0, x0T, h0T, b0);
    run_layer<128, 256, 156, 2, HPH0, HPH1>(smem, su, gA1, h0T, h1T, b1);
    run_layer< 64, 128,  78, 4, HPH1,   64>(smem, su, gA2, h1T, h2T, b2);

    // ---- final: out[b, l] = sum_d hT[d][l] ----
    float* outb = out + (size_t)b * 448;
    for (int l = tid; l < 448; l += NTHR) {
        const float* src; int stride, col;
        if (l < 256)      { src = h0T; stride = HPH0; col = l; }
        else if (l < 384) { src = h1T; stride = HPH1; col = l - 256; }
        else              { src = h2T; stride = 64;   col = l - 384; }
        float s = 0.f;
        #pragma unroll 8
        for (int d = 0; d < DIM; d++) s += src[d * stride + col];
        outb[l] = s;
    }
}

extern "C" void kernel_launch(void* const* d_in, const int* in_sizes, int n_in,
                              void* d_out, int out_size) {
    const void*  feat = d_in[0];
    const float* emb  = (const float*)d_in[1];
    const float* W0   = (const float*)d_in[2];
    const float* b0   = (const float*)d_in[3];
    const float* W1   = (const float*)d_in[4];
    const float* b1   = (const float*)d_in[5];
    const float* W2   = (const float*)d_in[6];
    const float* b2   = (const float*)d_in[7];
    float* out = (float*)d_out;

    prep_kernel<<<282, 256>>>(W0, W1, W2);
    cudaFuncSetAttribute(cin_mma_kernel,
                         cudaFuncAttributeMaxDynamicSharedMemorySize, SMEM_BYTES);
    cin_mma_kernel<<<BATCH, NTHR, SMEM_BYTES>>>(feat, emb, b0, b1, b2, out);
}

// round 10
// speedup vs baseline: 3.9708x; 1.3116x over previous
#include <cuda_runtime.h>
#include <cuda_fp16.h>
#include <cstdint>

#define FIELD 39
#define DIM   64
#define NTHR  512
#define BATCH 2048

// SMEM layout (bytes)
#define HP0  40
#define HPH0 264
#define SO_X0T 0                       // fp32 x0T [d][i], stride 40
#define SO_X0H 10240                   // fp16 x0 hi(6144)+lo(6144) [i<48][d]
#define SO_H0T 22528                   // fp32 h0T [d][j], stride 264 (67584 B)
#define SO_H1H 90112                   // fp16 h1 hi(16K)+lo(16K) [j<128][d]
#define SO_B   122880                  // B dbuf 2x16K; later g32 (19968)
#define SO_A   155648                  // A dbuf / scratch / GEMV ring (64K)
#define SMEM_BYTES 221184

// Prepped W^T fp16 tile images (swizzle baked).
__device__ __align__(16) unsigned short gA0[48u  * 8192];  // 128x64 tiles
__device__ __align__(16) unsigned short gA1[156u * 8192];  // 128x64 tiles
__device__ __align__(16) unsigned short gA2[78u  * 4096];  // 64x64 tiles

__device__ __forceinline__ uint32_t swz(uint32_t off) {
    return off ^ ((off >> 3) & 0x70);
}
__device__ __forceinline__ void ldm4(uint32_t a, uint32_t r[4]) {
    asm volatile("ldmatrix.sync.aligned.m8n8.x4.shared.b16 {%0,%1,%2,%3}, [%4];"
                 : "=r"(r[0]), "=r"(r[1]), "=r"(r[2]), "=r"(r[3]) : "r"(a));
}
__device__ __forceinline__ void mmah(float c[4], const uint32_t a[4],
                                     uint32_t b0, uint32_t b1) {
    asm volatile("mma.sync.aligned.m16n8k16.row.col.f32.f16.f16.f32 "
                 "{%0,%1,%2,%3},{%4,%5,%6,%7},{%8,%9},{%0,%1,%2,%3};"
                 : "+f"(c[0]), "+f"(c[1]), "+f"(c[2]), "+f"(c[3])
                 : "r"(a[0]), "r"(a[1]), "r"(a[2]), "r"(a[3]), "r"(b0), "r"(b1));
}
__device__ __forceinline__ void cpasync16(uint32_t s, const void* g) {
    asm volatile("cp.async.cg.shared.global [%0], [%1], 16;" :: "r"(s), "l"(g));
}
#define CP_COMMIT() asm volatile("cp.async.commit_group;")
#define CP_WAIT0()  asm volatile("cp.async.wait_group 0;")
#define CP_WAIT1()  asm volatile("cp.async.wait_group 1;")

__device__ __forceinline__ unsigned short hbits(__half h) {
    return *(unsigned short*)&h;
}
__device__ __forceinline__ uint32_t pack2h(float a, float b) {
    return (uint32_t)hbits(__float2half_rn(a)) |
           ((uint32_t)hbits(__float2half_rn(b)) << 16);
}
// packed split: hi = f16x2(a,b), lo = f16x2 of residuals
__device__ __forceinline__ uint32_t split2h2(float a, float b, uint32_t& lo) {
    const __half2 h = __floats2half2_rn(a, b);
    const float2 hf = __half22float2(h);
    const __half2 l = __floats2half2_rn(a - hf.x, b - hf.y);
    lo = *(const uint32_t*)&l;
    return *(const uint32_t*)&h;
}

// ---- prep: W -> swizzle-baked fp16 W^T tile images ----
__global__ void prep_kernel(const float* __restrict__ W0,
                            const float* __restrict__ W1,
                            const float* __restrict__ W2) {
    const int tile = blockIdx.x;
    const float* W; unsigned short* A; int K, Lv, kt, mt, rows;
    if (tile < 48)       { kt = tile >> 1; mt = tile & 1; W = W0; K = 1521; Lv = 256;
                           rows = 128; A = gA0 + (size_t)tile * 8192; }
    else if (tile < 204) { int u = tile - 48;  kt = u; mt = 0; W = W1; K = 9984; Lv = 128;
                           rows = 128; A = gA1 + (size_t)u * 8192; }
    else                 { int u = tile - 204; kt = u; mt = 0; W = W2; K = 4992; Lv = 64;
                           rows = 64;  A = gA2 + (size_t)u * 4096; }
    for (int it = threadIdx.x; it < rows * 8; it += blockDim.x) {
        const int row = it % rows, cg = it / rows;
        const int l = mt * 128 + row;
        uint32_t hw[4];
        #pragma unroll
        for (int p = 0; p < 4; p++) {
            float v0 = 0.f, v1 = 0.f;
            const int k0 = kt * 64 + cg * 8 + 2 * p;
            if (l < Lv) {
                if (k0     < K) v0 = W[(size_t)k0 * Lv + l];
                if (k0 + 1 < K) v1 = W[(size_t)(k0 + 1) * Lv + l];
            }
            hw[p] = pack2h(v0, v1);
        }
        const uint32_t sw = swz((uint32_t)(row * 128 + cg * 16));
        *(uint4*)((char*)A + sw) = make_uint4(hw[0], hw[1], hw[2], hw[3]);
    }
}

// ---- build one 64-k B chunk: B[d][k] = x0[i,d]*h[j,d], fp16 hi/lo ----
template<int FK, int HPREV>
__device__ __forceinline__ void build_b(char* smem, int t, uint32_t bst,
                                        const float* __restrict__ hprevT) {
    const int tid = threadIdx.x;
    const float* x0T = (const float*)(smem + SO_X0T);
    const int d = tid >> 3, g = tid & 7;
    const int kb = t * 64 + g * 8;
    float v[8];
    if (FK == FIELD) {
        #pragma unroll
        for (int e = 0; e < 8; e++) {
            const int k = kb + e, i = k / FIELD, j = k - i * FIELD;
            v[e] = x0T[d * HP0 + i] * x0T[d * HP0 + j];
        }
    } else {
        const int i = kb / FK, j0 = kb % FK;
        const float xv = x0T[d * HP0 + i];
        const float4 a = *(const float4*)(hprevT + d * HPREV + j0);
        const float4 b = *(const float4*)(hprevT + d * HPREV + j0 + 4);
        v[0]=xv*a.x; v[1]=xv*a.y; v[2]=xv*a.z; v[3]=xv*a.w;
        v[4]=xv*b.x; v[5]=xv*b.y; v[6]=xv*b.z; v[7]=xv*b.w;
    }
    uint32_t hw[4], lw[4];
    #pragma unroll
    for (int p = 0; p < 4; p++) hw[p] = split2h2(v[2*p], v[2*p+1], lw[p]);
    const uint32_t sw = swz((uint32_t)(d * 128 + g * 16));
    char* bb = smem + SO_B + bst;
    *(uint4*)(bb + sw)        = make_uint4(hw[0], hw[1], hw[2], hw[3]);
    *(uint4*)(bb + 8192 + sw) = make_uint4(lw[0], lw[1], lw[2], lw[3]);
}

// ---- one 64-k chunk of MMAs for this warp's 32x32 tile ----
template<int L>
__device__ __forceinline__ void chunk_mma(uint32_t su, uint32_t ast, uint32_t bst,
                                          int lrow, int dcol, int kk0, int kks,
                                          float acc[2][4][4]) {
    const int lane = threadIdx.x & 31;
    for (int kk = kk0; kk < kk0 + kks; kk++) {
        uint32_t ah[2][4], bh[2][4], bl[2][4];
        const uint32_t ch = (uint32_t)((kk * 16 + (lane >> 4) * 8) * 2);
        #pragma unroll
        for (int mi = 0; mi < 2; mi++) {
            const int l = lrow + mi * 16 + (lane & 15);
            const int mt = (L == 256) ? (l >> 7) : 0;
            const int r  = (L == 256) ? (l & 127) : l;
            ldm4(su + SO_A + ast + (uint32_t)mt * 16384u +
                 swz((uint32_t)(r * 128) + ch), ah[mi]);
        }
        #pragma unroll
        for (int nb = 0; nb < 2; nb++) {
            const int d = dcol + nb * 16 + (lane & 15);
            const uint32_t off = swz((uint32_t)(d * 128) + ch);
            ldm4(su + SO_B + bst + off, bh[nb]);
            ldm4(su + SO_B + bst + 8192 + off, bl[nb]);
        }
        #pragma unroll
        for (int mi = 0; mi < 2; mi++)
            #pragma unroll
            for (int j = 0; j < 4; j++) {
                const int nb = j >> 1, q = j & 1;
                mmah(acc[mi][j], ah[mi], bh[nb][q], bh[nb][q + 2]);
                mmah(acc[mi][j], ah[mi], bl[nb][q], bl[nb][q + 2]);
            }
    }
}

// ---- one CIN layer. EPI=0: fp32 [d][l] store. EPI=1: fp16 h1 + rowsums ----
template<int L, int FK, int NKT, int S, int HPREV, int HPOUT, int EPI>
__device__ void run_layer(char* smem, uint32_t su, const unsigned short* gA,
                          const float* __restrict__ hprevT, float* houtT,
                          const float* __restrict__ biasg, float* outAcc) {
    const int tid = threadIdx.x, wid = tid >> 5, lane = tid & 31;
    constexpr int NTL = L / 32, NTILES = NTL * 2;
    constexpr int KKS = 4 / S;
    constexpr uint32_t ASTB = (uint32_t)L * 128u;
    const int tile = wid % NTILES, slice = wid / NTILES;
    const int lrow = (tile % NTL) * 32, dcol = (tile / NTL) * 32;
    const int kk0 = slice * KKS;

    float acc[2][4][4];
    #pragma unroll
    for (int mi = 0; mi < 2; mi++)
        #pragma unroll
        for (int j = 0; j < 4; j++)
            #pragma unroll
            for (int q = 0; q < 4; q++) acc[mi][j][q] = 0.f;

    auto stage_a = [&](int t) {
        const uint32_t dst = su + SO_A + (uint32_t)(t & 1) * 32768u;
        const char* src = (const char*)gA + (size_t)t * ASTB;
        constexpr int N16 = (int)(ASTB / 16);
        for (int idx = tid; idx < N16; idx += NTHR)
            cpasync16(dst + (uint32_t)idx * 16, src + idx * 16);
        CP_COMMIT();
    };

    stage_a(0);
    build_b<FK, HPREV>(smem, 0, 0, hprevT);
    CP_WAIT0();
    __syncthreads();

    for (int t = 0; t < NKT; t++) {
        const bool more = (t + 1 < NKT);
        if (more) stage_a(t + 1);
        chunk_mma<L>(su, (uint32_t)(t & 1) * 32768u, (uint32_t)(t & 1) * 16384u,
                     lrow, dcol, kk0, KKS, acc);
        if (more) build_b<FK, HPREV>(smem, t + 1, ((t + 1) & 1) * 16384u, hprevT);
        CP_WAIT0();
        __syncthreads();
    }

    // ---- k-slice reduction via A region (idle now) ----
    if (S > 1) {
        if (slice != 0) {
            float4* dst = (float4*)(smem + SO_A +
                (size_t)(((slice - 1) * NTILES + tile) * 4096 + lane * 128));
            #pragma unroll
            for (int mi = 0; mi < 2; mi++)
                #pragma unroll
                for (int j = 0; j < 4; j++)
                    dst[mi * 4 + j] = *(float4*)acc[mi][j];
        }
        __syncthreads();
        if (slice == 0) {
            for (int s = 1; s < S; s++) {
                const float4* src = (const float4*)(smem + SO_A +
                    (size_t)(((s - 1) * NTILES + tile) * 4096 + lane * 128));
                #pragma unroll
                for (int mi = 0; mi < 2; mi++)
                    #pragma unroll
                    for (int j = 0; j < 4; j++) {
                        const float4 v = src[mi * 4 + j];
                        acc[mi][j][0] += v.x; acc[mi][j][1] += v.y;
                        acc[mi][j][2] += v.z; acc[mi][j][3] += v.w;
                    }
            }
        }
    }

    if (slice == 0) {
        if (EPI == 0) {
            // fp32 transposed store [d][l]
            const int g = lane >> 2, t4 = lane & 3;
            #pragma unroll
            for (int mi = 0; mi < 2; mi++) {
                const int la = lrow + mi * 16 + g;
                const float b0 = biasg[la], b1 = biasg[la + 8];
                #pragma unroll
                for (int j = 0; j < 4; j++) {
                    const int db = dcol + (j >> 1) * 16 + (j & 1) * 8 + 2 * t4;
                    houtT[db * HPOUT + la]           = acc[mi][j][0] + b0;
                    houtT[(db + 1) * HPOUT + la]     = acc[mi][j][1] + b0;
                    houtT[db * HPOUT + la + 8]       = acc[mi][j][2] + b1;
                    houtT[(db + 1) * HPOUT + la + 8] = acc[mi][j][3] + b1;
                }
            }
        } else {
            // fp16 hi/lo store [j][d] + rowsum partials
            const int g = lane >> 2, t4 = lane & 3;
            #pragma unroll
            for (int mi = 0; mi < 2; mi++) {
                const int la = lrow + mi * 16 + g;
                const float b0 = biasg[la], b1 = biasg[la + 8];
                float s0 = 0.f, s1 = 0.f;
                #pragma unroll
                for (int j = 0; j < 4; j++) {
                    const int db = dcol + (j >> 1) * 16 + (j & 1) * 8 + 2 * t4;
                    uint32_t lo, hi;
                    hi = split2h2(acc[mi][j][0] + b0, acc[mi][j][1] + b0, lo);
                    *(uint32_t*)(smem + SO_H1H + swz((uint32_t)(la * 128 + db * 2))) = hi;
                    *(uint32_t*)(smem + SO_H1H + 16384u + swz((uint32_t)(la * 128 + db * 2))) = lo;
                    hi = split2h2(acc[mi][j][2] + b1, acc[mi][j][3] + b1, lo);
                    *(uint32_t*)(smem + SO_H1H + swz((uint32_t)((la + 8) * 128 + db * 2))) = hi;
                    *(uint32_t*)(smem + SO_H1H + 16384u + swz((uint32_t)((la + 8) * 128 + db * 2))) = lo;
                    s0 += acc[mi][j][0] + acc[mi][j][1];
                    s1 += acc[mi][j][2] + acc[mi][j][3];
                }
                s0 += __shfl_xor_sync(0xffffffffu, s0, 1);
                s0 += __shfl_xor_sync(0xffffffffu, s0, 2);
                s1 += __shfl_xor_sync(0xffffffffu, s1, 1);
                s1 += __shfl_xor_sync(0xffffffffu, s1, 2);
                if (t4 == 0) {
                    outAcc[(dcol >> 5) * 128 + la]     = s0;
                    outAcc[(dcol >> 5) * 128 + la + 8] = s1;
                }
            }
        }
    }
    __syncthreads();
}

__global__ void __launch_bounds__(NTHR, 1)
cin_mma_kernel(const void* __restrict__ feat_ids_raw,
               const float* __restrict__ emb,
               const float* __restrict__ b0g, const float* __restrict__ b1g,
               const float* __restrict__ b2g, float* __restrict__ out) {
    extern __shared__ char smem[];
    const uint32_t su = (uint32_t)__cvta_generic_to_shared(smem);
    const int b = blockIdx.x, tid = threadIdx.x, wid = tid >> 5, lane = tid & 31;
    float* x0T = (float*)(smem + SO_X0T);
    float* h0T = (float*)(smem + SO_H0T);
    __shared__ long long sids[FIELD];
    __shared__ int is64flag;
    __shared__ float outAcc[2 * 128];
    __shared__ float gpart[256];

    if (tid == 0) {
        const unsigned int* w = (const unsigned int*)feat_ids_raw;
        int f = 1;
        #pragma unroll
        for (int t = 0; t < 32; t++) if (w[2*t+1] != 0u) { f = 0; break; }
        is64flag = f;
    }
    __syncthreads();
    if (tid < FIELD) {
        sids[tid] = is64flag
            ? ((const long long*)feat_ids_raw)[(size_t)b * FIELD + tid]
            : (long long)((const int*)feat_ids_raw)[(size_t)b * FIELD + tid];
    }
    __syncthreads();
    for (int t = tid; t < FIELD * DIM; t += NTHR) {
        const int i = t >> 6, d = t & 63;
        x0T[d * HP0 + i] = emb[(size_t)sids[i] * DIM + d];
    }
    if (tid < 64) x0T[tid * HP0 + FIELD] = 0.f;   // zero pad col (K padding)
    __syncthreads();
    // x0h: fp16 hi/lo [i<48][d] swizzled rows (pairs of adjacent d)
    for (int e = tid; e < 48 * 32; e += NTHR) {
        const int i = e >> 5, dp = (e & 31) * 2;
        float v0 = 0.f, v1 = 0.f;
        if (i < FIELD) { v0 = x0T[dp * HP0 + i]; v1 = x0T[(dp + 1) * HP0 + i]; }
        uint32_t lo;
        const uint32_t hi = split2h2(v0, v1, lo);
        const uint32_t off = swz((uint32_t)(i * 128 + dp * 2));
        *(uint32_t*)(smem + SO_X0H + off) = hi;
        *(uint32_t*)(smem + SO_X0H + 6144u + off) = lo;
    }
    __syncthreads();

    run_layer<256,  39,  24, 1, HP0,  HPH0, 0>(smem, su, gA0, x0T, h0T, b0g, outAcc);
    run_layer<128, 256, 156, 2, HPH0,    0, 1>(smem, su, gA1, h0T, (float*)0, b1g, outAcc);

    float* outb = out + (size_t)b * 448;
    if (tid < 128)
        outb[256 + tid] = outAcc[tid] + outAcc[128 + tid] + 64.f * b1g[tid];

    // ---- G = H1 (128xK64) x X0^T (48) : 3-product fp16 GEMM ----
    float* g32 = (float*)(smem + SO_B);
    if (wid < 8) {
        const int jb = wid * 16;
        float ga[6][4];
        #pragma unroll
        for (int u = 0; u < 6; u++)
            #pragma unroll
            for (int q = 0; q < 4; q++) ga[u][q] = 0.f;
        #pragma unroll
        for (int kk = 0; kk < 4; kk++) {
            const uint32_t ch = (uint32_t)((kk * 16 + (lane >> 4) * 8) * 2);
            uint32_t ah[4], al[4], bh[3][4], bl[3][4];
            ldm4(su + SO_H1H + swz((uint32_t)((jb + (lane & 15)) * 128) + ch), ah);
            ldm4(su + SO_H1H + 16384u + swz((uint32_t)((jb + (lane & 15)) * 128) + ch), al);
            #pragma unroll
            for (int nb = 0; nb < 3; nb++) {
                const uint32_t off = swz((uint32_t)((nb * 16 + (lane & 15)) * 128) + ch);
                ldm4(su + SO_X0H + off, bh[nb]);
                ldm4(su + SO_X0H + 6144u + off, bl[nb]);
            }
            #pragma unroll
            for (int nb = 0; nb < 3; nb++)
                #pragma unroll
                for (int q = 0; q < 2; q++) {
                    float* c = ga[nb * 2 + q];
                    mmah(c, ah, bh[nb][q], bh[nb][q + 2]);
                    mmah(c, ah, bl[nb][q], bl[nb][q + 2]);
                    mmah(c, al, bh[nb][q], bh[nb][q + 2]);
                }
        }
        const int r0 = jb + (lane >> 2);
        #pragma unroll
        for (int nb = 0; nb < 3; nb++)
            #pragma unroll
            for (int q = 0; q < 2; q++) {
                const int i0 = nb * 16 + q * 8 + 2 * (lane & 3);
                const float* c = ga[nb * 2 + q];
                if (i0 < FIELD) {
                    g32[i0 * 128 + r0]     = c[0];
                    g32[i0 * 128 + r0 + 8] = c[2];
                }
                if (i0 + 1 < FIELD) {
                    g32[(i0 + 1) * 128 + r0]     = c[1];
                    g32[(i0 + 1) * 128 + r0 + 8] = c[3];
                }
            }
    }
    __syncthreads();
    // pack g -> fp16 hi/lo pairs
    uint32_t* gh2 = (uint32_t*)(smem + SO_X0T);
    uint32_t* gl2 = (uint32_t*)(smem + SO_X0H);
    for (int idx = tid; idx < 2496; idx += NTHR) {
        uint32_t lo;
        gh2[idx] = split2h2(g32[2 * idx], g32[2 * idx + 1], lo);
        gl2[idx] = lo;
    }
    __syncthreads();

    // ---- GEMV: out2[l] = sum_p W2h[p,l] * g[p], via HMMA n8 broadcast ----
    {
        auto stageg = [&](int st) {
            const int t0 = st * 4;
            const int n16 = (78 - t0 < 4 ? 78 - t0 : 4) * 512;
            const uint32_t dst = su + SO_A + (uint32_t)(st & 1) * 32768u;
            const char* src = (const char*)gA2 + (size_t)t0 * 8192;
            for (int idx = tid; idx < n16; idx += NTHR)
                cpasync16(dst + (uint32_t)idx * 16, src + idx * 16);
            CP_COMMIT();
        };
        const int tw = wid & 3, mb = wid >> 2;
        float gac[4] = {0.f, 0.f, 0.f, 0.f};
        stageg(0);
        for (int st = 0; st < 20; st++) {
            if (st + 1 < 20) { stageg(st + 1); CP_WAIT1(); }
            else CP_WAIT0();
            __syncthreads();
            const int gt = st * 4 + tw;
            if (gt < 78) {
                const uint32_t abase = su + SO_A + (uint32_t)(st & 1) * 32768u +
                                       (uint32_t)tw * 8192u;
                #pragma unroll
                for (int ks = 0; ks < 4; ks++) {
                    uint32_t a[4];
                    ldm4(abase + swz((uint32_t)((mb * 16 + (lane & 15)) * 128 +
                         (ks * 16 + (lane >> 4) * 8) * 2)), a);
                    const int gi = gt * 32 + ks * 8 + (lane & 3);
                    mmah(gac, a, gh2[gi], gh2[gi + 4]);
                    mmah(gac, a, gl2[gi], gl2[gi + 4]);
                }
            }
            __syncthreads();
        }
        if ((lane & 3) == 0) {
            gpart[wid * 16 + (lane >> 2)]     = gac[0];
            gpart[wid * 16 + (lane >> 2) + 8] = gac[2];
        }
    }
    __syncthreads();
    if (tid < 64) {
        const int mb = tid >> 4, r = tid & 15;
        const float s = gpart[(mb)      * 16 + r] + gpart[(mb + 4)  * 16 + r] +
                        gpart[(mb + 8)  * 16 + r] + gpart[(mb + 12) * 16 + r];
        outb[384 + tid] = s + 64.f * b2g[tid];
    }

    // ---- out[0..256) = sum_d h0T ----
    for (int l = tid; l < 256; l += NTHR) {
        float s = 0.f;
        #pragma unroll 8
        for (int d = 0; d < DIM; d++) s += h0T[d * HPH0 + l];
        outb[l] = s;
    }
}

extern "C" void kernel_launch(void* const* d_in, const int* in_sizes, int n_in,
                              void* d_out, int out_size) {
    const void*  feat = d_in[0];
    const float* emb  = (const float*)d_in[1];
    const float* W0   = (const float*)d_in[2];
    const float* b0   = (const float*)d_in[3];
    const float* W1   = (const float*)d_in[4];
    const float* b1   = (const float*)d_in[5];
    const float* W2   = (const float*)d_in[6];
    const float* b2   = (const float*)d_in[7];
    float* out = (float*)d_out;

    prep_kernel<<<282, 256>>>(W0, W1, W2);
    cudaFuncSetAttribute(cin_mma_kernel,
                         cudaFuncAttributeMaxDynamicSharedMemorySize, SMEM_BYTES);
    cin_mma_kernel<<<BATCH, NTHR, SMEM_BYTES>>>(feat, emb, b0, b1, b2, out);
}